// round 4
// baseline (speedup 1.0000x reference)
#include <cuda_runtime.h>
#include <math.h>
#include <stdint.h>

#define NTOK 16384
#define DM   2048
#define NE   64
#define CAP  640
#define BT   128
#define KB   16
#define NCHUNK (DM / KB)   // 128

#define FMA2(c, a, b) \
    asm("fma.rn.f32x2 %0, %1, %2, %0;" : "+l"(c) : "l"(a), "l"(b))

// ---------------- device scratch ----------------
__device__ int   g_e12[NTOK];
__device__ float g_w12[2 * NTOK];
__device__ int   g_cnt1[NE];
__device__ float g_counts[NE];
__device__ float g_zsum;

// ---------------- init ----------------
__global__ void init_kernel() {
    int t = threadIdx.x;
    if (t < NE) { g_cnt1[t] = 0; g_counts[t] = 0.0f; }
    if (t == 0) g_zsum = 0.0f;
}

// ---------------- stage A: packed-f32x2 GEMM + fused epilogue ----------------
__global__ __launch_bounds__(256) void gemm_router(
    const float* __restrict__ x, const float* __restrict__ W,
    float* __restrict__ out_rw)
{
    __shared__ __align__(16) float xs[2][KB][BT];    // xs[k][token]
    __shared__ __align__(16) float wsd[2][KB][128];  // duplicated: [k][2e],[2e+1]=W[e][k]
    __shared__ float ls[64][65];
    __shared__ float zred[8];

    const int tid = threadIdx.x;
    const int tg  = tid & 15;          // token group: 8 tokens
    const int eg  = tid >> 4;          // expert group: 4 experts
    const int bt0 = blockIdx.x * BT;

    uint64_t acc[4][4];                // [token-pair][expert], packed f32x2
#pragma unroll
    for (int p = 0; p < 4; p++)
#pragma unroll
        for (int j = 0; j < 4; j++) acc[p][j] = 0ull;

    // ---- load chunk 0 ----
#pragma unroll
    for (int i = 0; i < 2; i++) {
        int idx = i * 256 + tid;
        int t = idx >> 2, kq = idx & 3;
        float4 v = *reinterpret_cast<const float4*>(x + (size_t)(bt0 + t) * DM + kq * 4);
        xs[0][kq * 4 + 0][t] = v.x; xs[0][kq * 4 + 1][t] = v.y;
        xs[0][kq * 4 + 2][t] = v.z; xs[0][kq * 4 + 3][t] = v.w;
    }
    {
        int e = tid >> 2, kq = tid & 3;
        float4 v = *reinterpret_cast<const float4*>(W + (size_t)e * DM + kq * 4);
        wsd[0][kq * 4 + 0][2 * e] = v.x; wsd[0][kq * 4 + 0][2 * e + 1] = v.x;
        wsd[0][kq * 4 + 1][2 * e] = v.y; wsd[0][kq * 4 + 1][2 * e + 1] = v.y;
        wsd[0][kq * 4 + 2][2 * e] = v.z; wsd[0][kq * 4 + 2][2 * e + 1] = v.z;
        wsd[0][kq * 4 + 3][2 * e] = v.w; wsd[0][kq * 4 + 3][2 * e + 1] = v.w;
    }
    __syncthreads();

    // ---- main K loop, double buffered ----
    for (int kc = 0; kc < NCHUNK; kc++) {
        const int b = kc & 1;
        float4 px0, px1, pw;
        const bool more = (kc + 1 < NCHUNK);
        if (more) {
            const int k0 = (kc + 1) * KB;
            {
                int idx = tid;
                int t = idx >> 2, kq = idx & 3;
                px0 = *reinterpret_cast<const float4*>(x + (size_t)(bt0 + t) * DM + k0 + kq * 4);
            }
            {
                int idx = 256 + tid;
                int t = idx >> 2, kq = idx & 3;
                px1 = *reinterpret_cast<const float4*>(x + (size_t)(bt0 + t) * DM + k0 + kq * 4);
            }
            {
                int e = tid >> 2, kq = tid & 3;
                pw = *reinterpret_cast<const float4*>(W + (size_t)e * DM + k0 + kq * 4);
            }
        }

#pragma unroll
        for (int kk = 0; kk < KB; kk++) {
            const ulonglong2* xp = reinterpret_cast<const ulonglong2*>(&xs[b][kk][tg * 8]);
            ulonglong2 xa = xp[0], xb = xp[1];
            const ulonglong2* wp = reinterpret_cast<const ulonglong2*>(&wsd[b][kk][eg * 8]);
            ulonglong2 w0 = wp[0], w1 = wp[1];
            uint64_t P[4]  = {xa.x, xa.y, xb.x, xb.y};
            uint64_t Wd[4] = {w0.x, w0.y, w1.x, w1.y};
#pragma unroll
            for (int p = 0; p < 4; p++)
#pragma unroll
                for (int j = 0; j < 4; j++)
                    FMA2(acc[p][j], P[p], Wd[j]);
        }

        if (more) {
            const int nb = b ^ 1;
            {
                int idx = tid; int t = idx >> 2, kq = idx & 3;
                xs[nb][kq * 4 + 0][t] = px0.x; xs[nb][kq * 4 + 1][t] = px0.y;
                xs[nb][kq * 4 + 2][t] = px0.z; xs[nb][kq * 4 + 3][t] = px0.w;
            }
            {
                int idx = 256 + tid; int t = idx >> 2, kq = idx & 3;
                xs[nb][kq * 4 + 0][t] = px1.x; xs[nb][kq * 4 + 1][t] = px1.y;
                xs[nb][kq * 4 + 2][t] = px1.z; xs[nb][kq * 4 + 3][t] = px1.w;
            }
            {
                int e = tid >> 2, kq = tid & 3;
                wsd[nb][kq * 4 + 0][2 * e] = pw.x; wsd[nb][kq * 4 + 0][2 * e + 1] = pw.x;
                wsd[nb][kq * 4 + 1][2 * e] = pw.y; wsd[nb][kq * 4 + 1][2 * e + 1] = pw.y;
                wsd[nb][kq * 4 + 2][2 * e] = pw.z; wsd[nb][kq * 4 + 2][2 * e + 1] = pw.z;
                wsd[nb][kq * 4 + 3][2 * e] = pw.w; wsd[nb][kq * 4 + 3][2 * e + 1] = pw.w;
            }
        }
        __syncthreads();
    }

    // ---- epilogue: softmax + top2 per row, two 64-row halves ----
    const int warp = tid >> 5, lane = tid & 31;
    float zacc = 0.0f;

    for (int h = 0; h < 2; h++) {
        __syncthreads();
        if ((tg >> 3) == h) {
            const int trow = (tg & 7) * 8;
#pragma unroll
            for (int p = 0; p < 4; p++)
#pragma unroll
                for (int j = 0; j < 4; j++) {
                    ls[trow + 2 * p][eg * 4 + j]     = __uint_as_float((uint32_t)acc[p][j]);
                    ls[trow + 2 * p + 1][eg * 4 + j] = __uint_as_float((uint32_t)(acc[p][j] >> 32));
                }
        }
        __syncthreads();

        for (int j = 0; j < 8; j++) {
            const int r = warp * 8 + j;
            const int token = bt0 + h * 64 + r;
            float a  = ls[r][lane];
            float bv = ls[r][lane + 32];
            zacc += a * a + bv * bv;

            float mx = fmaxf(a, bv);
#pragma unroll
            for (int off = 16; off; off >>= 1)
                mx = fmaxf(mx, __shfl_xor_sync(0xffffffffu, mx, off));

            float pa = expf(a - mx), pb = expf(bv - mx);
            float s = pa + pb;
#pragma unroll
            for (int off = 16; off; off >>= 1)
                s += __shfl_xor_sync(0xffffffffu, s, off);

            out_rw[(size_t)token * NE + lane]      = pa / s;
            out_rw[(size_t)token * NE + lane + 32] = pb / s;

            float v1, v2; int i1, i2;
            if (pa >= pb) { v1 = pa; i1 = lane;      v2 = pb; i2 = lane + 32; }
            else          { v1 = pb; i1 = lane + 32; v2 = pa; i2 = lane; }

#pragma unroll
            for (int off = 16; off; off >>= 1) {
                float o1 = __shfl_xor_sync(0xffffffffu, v1, off);
                int  oi1 = __shfl_xor_sync(0xffffffffu, i1, off);
                float o2 = __shfl_xor_sync(0xffffffffu, v2, off);
                int  oi2 = __shfl_xor_sync(0xffffffffu, i2, off);
                bool awins = (v1 > o1) || (v1 == o1 && i1 < oi1);
                if (awins) {
                    bool keep = (v2 > o1) || (v2 == o1 && i2 < oi1);
                    if (!keep) { v2 = o1; i2 = oi1; }
                } else {
                    bool btwo = (o2 > v1) || (o2 == v1 && oi2 < i1);
                    float nv2; int ni2;
                    if (btwo) { nv2 = o2; ni2 = oi2; }
                    else      { nv2 = v1; ni2 = i1; }
                    v1 = o1; i1 = oi1; v2 = nv2; i2 = ni2;
                }
            }

            if (lane == 0) {
                float w1 = v1 / s, w2 = v2 / s;
                float sw = w1 + w2;
                float w1n = w1 / (sw + 1e-8f);
                float w2n = w2 / (sw + 1e-8f);
                g_e12[token] = i1 | (i2 << 8);
                g_w12[2 * token]     = w1n;
                g_w12[2 * token + 1] = w2n;
                atomicAdd(&g_cnt1[i1], 1);
            }
        }
    }

    // ---- z-loss partial reduce ----
#pragma unroll
    for (int off = 16; off; off >>= 1)
        zacc += __shfl_xor_sync(0xffffffffu, zacc, off);
    if (lane == 0) zred[warp] = zacc;
    __syncthreads();
    if (warp == 0) {
        float t = (lane < 8) ? zred[lane] : 0.0f;
#pragma unroll
        for (int off = 4; off; off >>= 1)
            t += __shfl_xor_sync(0xffffffffu, t, off);
        if (lane == 0) atomicAdd(&g_zsum, t);
    }
}

// ---------------- stage B: dispatch mask + normalized counts ----------------
__global__ __launch_bounds__(256) void dispatch_kernel(float* __restrict__ out_nd)
{
    const int gt = blockIdx.x * 256 + threadIdx.x;
    const int token = gt >> 4;
    const int c4 = gt & 15;
    if (token >= NTOK) return;

    const int e12 = g_e12[token];
    const int e1 = e12 & 0xff, e2 = (e12 >> 8) & 0xff;
    const float w1n = g_w12[2 * token];
    const float w2n = g_w12[2 * token + 1];
    const bool acc2 = (g_cnt1[e2] < CAP);
    const float den = w1n + (acc2 ? w2n : 0.0f) + 1e-8f;
    const float d1 = w1n / den;
    const float d2 = acc2 ? (w2n / den) : 0.0f;

    float4 v = make_float4(0.f, 0.f, 0.f, 0.f);
    const int c0 = c4 * 4;
    int r1 = e1 - c0;
    if (r1 == 0) v.x = d1; else if (r1 == 1) v.y = d1;
    else if (r1 == 2) v.z = d1; else if (r1 == 3) v.w = d1;
    int r2 = e2 - c0;
    if (r2 == 0) v.x = d2; else if (r2 == 1) v.y = d2;
    else if (r2 == 2) v.z = d2; else if (r2 == 3) v.w = d2;

    *reinterpret_cast<float4*>(out_nd + (size_t)token * NE + c0) = v;

    if (c4 == 0) {
        atomicAdd(&g_counts[e1], d1);
        if (acc2) atomicAdd(&g_counts[e2], d2);
    }
}

// ---------------- stage C: scalar loss ----------------
__global__ void loss_kernel(float* __restrict__ out)
{
    const int lane = threadIdx.x;
    const float invN = 1.0f / (float)NTOK;
    const float tgt = 512.0f / (float)NTOK;
    float d0 = g_counts[lane] * invN - tgt;
    float d1 = g_counts[lane + 32] * invN - tgt;
    float s = d0 * d0 + d1 * d1;
#pragma unroll
    for (int off = 16; off; off >>= 1)
        s += __shfl_xor_sync(0xffffffffu, s, off);
    if (lane == 0) {
        float lb = s / 64.0f;
        float z = g_zsum / (float)((size_t)NTOK * NE);
        out[(size_t)2 * NTOK * NE] = 1e-3f * z + 1e-3f * lb;
    }
}

// ---------------- launch ----------------
extern "C" void kernel_launch(void* const* d_in, const int* in_sizes, int n_in,
                              void* d_out, int out_size)
{
    const float* x = (const float*)d_in[0];
    const float* W = (const float*)d_in[1];
    if (n_in >= 2 && in_sizes[0] == NE * DM) {
        x = (const float*)d_in[1];
        W = (const float*)d_in[0];
    }
    float* out = (float*)d_out;

    init_kernel<<<1, 64>>>();
    gemm_router<<<NTOK / BT, 256>>>(x, W, out);
    dispatch_kernel<<<(NTOK * 16) / 256, 256>>>(out + (size_t)NTOK * NE);
    loss_kernel<<<1, 32>>>(out);
}